// round 2
// baseline (speedup 1.0000x reference)
#include <cuda_runtime.h>

#define D_DIM 256
#define BM    128   // rows per block
#define BKC   128   // codes per chunk
#define BD    64    // d-slice per smem tile

#define FLT_BIG 3.402823466e+38f

// scratch (no allocations allowed)
__device__ float g_rownorm[32768];
__device__ float g_codenorm[1024];
__device__ int   g_bestidx[32768];
__device__ float g_partial[8192];

// ---------------------------------------------------------------------------
// warp-per-row squared L2 norms (rows of length 256)
// ---------------------------------------------------------------------------
__global__ void norms_kernel(const float* __restrict__ src,
                             float* __restrict__ dst, int nrows)
{
    int gw   = (blockIdx.x * blockDim.x + threadIdx.x) >> 5;
    int lane = threadIdx.x & 31;
    if (gw >= nrows) return;
    const float4* p = (const float4*)(src + (size_t)gw * D_DIM);
    float s = 0.f;
#pragma unroll
    for (int i = 0; i < 2; ++i) {
        float4 v = p[lane + 32 * i];
        s += v.x * v.x + v.y * v.y + v.z * v.z + v.w * v.w;
    }
#pragma unroll
    for (int o = 16; o > 0; o >>= 1) s += __shfl_xor_sync(0xffffffffu, s, o);
    if (lane == 0) dst[gw] = s;
}

// ---------------------------------------------------------------------------
// main kernel: 128x128 distance tile, 8x8 per-thread micro-tile, fused argmin
// dist[n,k] = fl( fl(a_n + b_k) - 2 * dot(x_n, e_k) )   (matches reference)
// ---------------------------------------------------------------------------
__global__ void __launch_bounds__(256, 2)
vq_argmin_kernel(const float* __restrict__ x, const float* __restrict__ cb,
                 const float* __restrict__ rown, const float* __restrict__ cbn,
                 int* __restrict__ bestidx, int K)
{
    extern __shared__ float smem[];
    float* sx = smem;            // [BD][BM]  (d-major, transposed)
    float* se = smem + BD * BM;  // [BD][BKC]

    int tid = threadIdx.x;
    int tx = tid & 15, ty = tid >> 4;
    int rowBase = blockIdx.x * BM;

    float an[8];
#pragma unroll
    for (int i = 0; i < 4; ++i) {
        an[i]     = rown[rowBase + 4 * ty + i];
        an[i + 4] = rown[rowBase + 64 + 4 * ty + i];
    }

    float bestd[8]; int bestk[8];
#pragma unroll
    for (int i = 0; i < 8; ++i) { bestd[i] = FLT_BIG; bestk[i] = 0; }

    int lr = tid >> 1;        // load row 0..127 (2 threads per row)
    int lh = (tid & 1) * 8;   // which 8 float4s along d

    for (int kc = 0; kc < K; kc += BKC) {
        float acc[8][8];
#pragma unroll
        for (int i = 0; i < 8; ++i)
#pragma unroll
            for (int j = 0; j < 8; ++j) acc[i][j] = 0.f;

        for (int dc = 0; dc < D_DIM; dc += BD) {
            __syncthreads();   // previous compute reads done
            const float4* xp = (const float4*)(x  + (size_t)(rowBase + lr) * D_DIM + dc);
            const float4* ep = (const float4*)(cb + (size_t)(kc      + lr) * D_DIM + dc);
#pragma unroll
            for (int it = 0; it < 8; ++it) {
                float4 v = xp[lh + it];
                int d = (lh + it) * 4;
                sx[(d + 0) * BM + lr] = v.x; sx[(d + 1) * BM + lr] = v.y;
                sx[(d + 2) * BM + lr] = v.z; sx[(d + 3) * BM + lr] = v.w;
                float4 w = ep[lh + it];
                se[(d + 0) * BKC + lr] = w.x; se[(d + 1) * BKC + lr] = w.y;
                se[(d + 2) * BKC + lr] = w.z; se[(d + 3) * BKC + lr] = w.w;
            }
            __syncthreads();
#pragma unroll 8
            for (int d = 0; d < BD; ++d) {
                float4 a0 = *(const float4*)&sx[d * BM  + 4 * ty];
                float4 a1 = *(const float4*)&sx[d * BM  + 64 + 4 * ty];
                float4 b0 = *(const float4*)&se[d * BKC + 4 * tx];
                float4 b1 = *(const float4*)&se[d * BKC + 64 + 4 * tx];
                float a[8] = {a0.x, a0.y, a0.z, a0.w, a1.x, a1.y, a1.z, a1.w};
                float b[8] = {b0.x, b0.y, b0.z, b0.w, b1.x, b1.y, b1.z, b1.w};
#pragma unroll
                for (int i = 0; i < 8; ++i)
#pragma unroll
                    for (int j = 0; j < 8; ++j)
                        acc[i][j] = fmaf(a[i], b[j], acc[i][j]);
            }
        }

        float bn[8];
#pragma unroll
        for (int j = 0; j < 4; ++j) {
            bn[j]     = cbn[kc + 4 * tx + j];
            bn[j + 4] = cbn[kc + 64 + 4 * tx + j];
        }
        // epilogue: distances + running argmin (ascending code index => strict <
        // keeps the first/lowest index, matching jnp.argmin tie-break)
#pragma unroll
        for (int i = 0; i < 8; ++i) {
#pragma unroll
            for (int j = 0; j < 8; ++j) {
                float t    = an[i] + bn[j];
                float dist = t - 2.0f * acc[i][j];
                int   kk   = kc + ((j < 4) ? (4 * tx + j) : (64 + 4 * tx + (j - 4)));
                if (dist < bestd[i]) { bestd[i] = dist; bestk[i] = kk; }
            }
        }
    }

    // cross-thread (over tx) argmin reduction per row, smem reuse
    __syncthreads();
    float* redd = smem;                    // [128][16]
    int*   redk = (int*)(smem + 2048);     // [128][16]
#pragma unroll
    for (int i = 0; i < 8; ++i) {
        int r = (i < 4) ? (4 * ty + i) : (64 + 4 * ty + (i - 4));
        redd[r * 16 + tx] = bestd[i];
        redk[r * 16 + tx] = bestk[i];
    }
    __syncthreads();
    if (tid < 128) {
        float bd = redd[tid * 16];
        int   bk = redk[tid * 16];
#pragma unroll
        for (int t = 1; t < 16; ++t) {
            float d2 = redd[tid * 16 + t];
            int   k2 = redk[tid * 16 + t];
            if (d2 < bd || (d2 == bd && k2 < bk)) { bd = d2; bk = k2; }
        }
        bestidx[rowBase + tid] = bk;
    }
}

// ---------------------------------------------------------------------------
// gather quantized rows, write outputs, deterministic per-block loss partials
// ---------------------------------------------------------------------------
__global__ void gather_kernel(const float* __restrict__ x, const float* __restrict__ cb,
                              const int* __restrict__ idx,
                              float* __restrict__ outq, float* __restrict__ outidx,
                              float* __restrict__ partial, int N)
{
    __shared__ float ssum[8];
    int gw   = (blockIdx.x * blockDim.x + threadIdx.x) >> 5;
    int lane = threadIdx.x & 31;
    float s = 0.f;
    if (gw < N) {
        int k = idx[gw];
        const float4* cp = (const float4*)(cb + (size_t)k * D_DIM);
        const float4* xp = (const float4*)(x + (size_t)gw * D_DIM);
        float4* op = (float4*)(outq + (size_t)gw * D_DIM);
#pragma unroll
        for (int i = 0; i < 2; ++i) {
            float4 q = cp[lane + 32 * i];
            float4 v = xp[lane + 32 * i];
            float dx = q.x - v.x, dy = q.y - v.y, dz = q.z - v.z, dw = q.w - v.w;
            s += dx * dx + dy * dy + dz * dz + dw * dw;
            op[lane + 32 * i] = q;
        }
        if (lane == 0 && outidx) outidx[gw] = (float)k;
    }
#pragma unroll
    for (int o = 16; o > 0; o >>= 1) s += __shfl_xor_sync(0xffffffffu, s, o);
    int w = threadIdx.x >> 5;
    if (lane == 0) ssum[w] = s;
    __syncthreads();
    if (threadIdx.x == 0) {
        float t = 0.f;
        for (int i = 0; i < 8; ++i) t += ssum[i];
        partial[blockIdx.x] = t;
    }
}

__global__ void loss_kernel(const float* __restrict__ partial, int n,
                            float* __restrict__ lossOut, float inv)
{
    int lane = threadIdx.x & 31;
    float s = 0.f;
    for (int i = lane; i < n; i += 32) s += partial[i];
#pragma unroll
    for (int o = 16; o > 0; o >>= 1) s += __shfl_xor_sync(0xffffffffu, s, o);
    if (lane == 0 && lossOut) *lossOut = s * inv;
}

// ---------------------------------------------------------------------------
extern "C" void kernel_launch(void* const* d_in, const int* in_sizes, int n_in,
                              void* d_out, int out_size)
{
    const float* x  = (const float*)d_in[0];
    const float* cb = (const float*)d_in[1];
    int N = in_sizes[0] / D_DIM;   // 32768
    int K = in_sizes[1] / D_DIM;   // 1024

    float* out  = (float*)d_out;
    float* outq = out;
    long long qn  = (long long)N * D_DIM;
    long long rem = (long long)out_size - qn;
    float* outidx  = nullptr;
    float* outloss = nullptr;
    if (rem >= (long long)N) {
        outidx = out + qn;
        if (rem >= (long long)N + 1) outloss = out + qn + N;
    } else if (rem >= 1) {
        outloss = out + qn;
    }

    float *rown, *cbn, *part;
    int* bidx;
    cudaGetSymbolAddress((void**)&rown, g_rownorm);
    cudaGetSymbolAddress((void**)&cbn,  g_codenorm);
    cudaGetSymbolAddress((void**)&bidx, g_bestidx);
    cudaGetSymbolAddress((void**)&part, g_partial);

    int warpBlocksN = (N * 32 + 255) / 256;
    int warpBlocksK = (K * 32 + 255) / 256;

    norms_kernel<<<warpBlocksN, 256>>>(x,  rown, N);
    norms_kernel<<<warpBlocksK, 256>>>(cb, cbn,  K);

    cudaFuncSetAttribute(vq_argmin_kernel,
                         cudaFuncAttributeMaxDynamicSharedMemorySize, 65536);
    vq_argmin_kernel<<<N / BM, 256, 65536>>>(x, cb, rown, cbn, bidx, K);

    gather_kernel<<<warpBlocksN, 256>>>(x, cb, bidx, outq, outidx, part, N);
    loss_kernel<<<1, 32>>>(part, warpBlocksN, outloss, 1.0f / (float)((long long)N * D_DIM));
}

// round 3
// speedup vs baseline: 3.2769x; 3.2769x over previous
#include <cuda_runtime.h>
#include <cuda_bf16.h>
#include <cstdint>

#define D_DIM 256
#define FLT_BIG 3.402823466e+38f

// scratch (static device globals; no allocations)
__device__ __nv_bfloat16 g_cbb[1024 * 256];
__device__ float g_codenorm[1024];
__device__ int   g_cand[32768 * 8];
__device__ int   g_bestidx[32768];
__device__ float g_partial[8192];

// ---------------------------------------------------------------------------
// PTX helpers
// ---------------------------------------------------------------------------
__device__ __forceinline__ void ldsm4(uint32_t addr, uint32_t& r0, uint32_t& r1,
                                      uint32_t& r2, uint32_t& r3) {
    asm volatile("ldmatrix.sync.aligned.m8n8.x4.shared.b16 {%0,%1,%2,%3}, [%4];"
                 : "=r"(r0), "=r"(r1), "=r"(r2), "=r"(r3) : "r"(addr));
}
__device__ __forceinline__ void mma16816(float* c, const uint32_t* a,
                                         uint32_t b0, uint32_t b1) {
    asm volatile(
        "mma.sync.aligned.m16n8k16.row.col.f32.bf16.bf16.f32 "
        "{%0,%1,%2,%3}, {%4,%5,%6,%7}, {%8,%9}, {%0,%1,%2,%3};"
        : "+f"(c[0]), "+f"(c[1]), "+f"(c[2]), "+f"(c[3])
        : "r"(a[0]), "r"(a[1]), "r"(a[2]), "r"(a[3]), "r"(b0), "r"(b1));
}
__device__ __forceinline__ void cpasync16(uint32_t dst, const void* src) {
    asm volatile("cp.async.cg.shared.global [%0], [%1], 16;" :: "r"(dst), "l"(src));
}
__device__ __forceinline__ void cpcommit() { asm volatile("cp.async.commit_group;"); }
__device__ __forceinline__ void cpwait1()  { asm volatile("cp.async.wait_group 1;"); }

__device__ __forceinline__ void ins3(float s, int k,
                                     float& v0, float& v1, float& v2,
                                     int& k0, int& k1, int& k2) {
    if (s < v2) {
        if (s < v0)      { v2 = v1; k2 = k1; v1 = v0; k1 = k0; v0 = s; k0 = k; }
        else if (s < v1) { v2 = v1; k2 = k1; v1 = s;  k1 = k; }
        else             { v2 = s;  k2 = k; }
    }
}

// ---------------------------------------------------------------------------
// prep: codebook -> bf16, code norms (fp32)
// ---------------------------------------------------------------------------
__global__ void prep_cb_kernel(const float* __restrict__ cb,
                               __nv_bfloat16* __restrict__ cbb,
                               float* __restrict__ cbn)
{
    int gw   = (blockIdx.x * blockDim.x + threadIdx.x) >> 5;   // code id
    int lane = threadIdx.x & 31;
    if (gw >= 1024) return;
    const float4* p = (const float4*)(cb + (size_t)gw * D_DIM);
    float4 v0 = p[lane * 2], v1 = p[lane * 2 + 1];
    float s = v0.x*v0.x + v0.y*v0.y + v0.z*v0.z + v0.w*v0.w
            + v1.x*v1.x + v1.y*v1.y + v1.z*v1.z + v1.w*v1.w;
#pragma unroll
    for (int o = 16; o > 0; o >>= 1) s += __shfl_xor_sync(0xffffffffu, s, o);
    if (lane == 0) cbn[gw] = s;
    __nv_bfloat162 b0 = __floats2bfloat162_rn(v0.x, v0.y);
    __nv_bfloat162 b1 = __floats2bfloat162_rn(v0.z, v0.w);
    __nv_bfloat162 b2 = __floats2bfloat162_rn(v1.x, v1.y);
    __nv_bfloat162 b3 = __floats2bfloat162_rn(v1.z, v1.w);
    uint4 u;
    u.x = *(uint32_t*)&b0; u.y = *(uint32_t*)&b1;
    u.z = *(uint32_t*)&b2; u.w = *(uint32_t*)&b3;
    *(uint4*)(cbb + (size_t)gw * D_DIM + lane * 8) = u;
}

// ---------------------------------------------------------------------------
// coarse: bf16 tensor-core distance pass, global top-8 candidates per row
//   block = 128 rows x (all 1024 codes in 8 chunks of 128)
//   smem: SX 64KB (x tile, full d, bf16, swizzled) | SE 2x16KB (cb 64-d slice)
//         | SCBN 4KB
// ---------------------------------------------------------------------------
#define CO_SMEM (65536 + 32768 + 4096)

__global__ void __launch_bounds__(256, 2)
coarse_kernel(const float* __restrict__ x, const __nv_bfloat16* __restrict__ cbb,
              const float* __restrict__ cbn, int* __restrict__ cand)
{
    extern __shared__ char sm[];
    const uint32_t smb = (uint32_t)__cvta_generic_to_shared(sm);
    float* SCBN = (float*)(sm + 98304);

    const int tid  = threadIdx.x;
    const int lane = tid & 31, wid = tid >> 5;
    const int gid  = lane >> 2, tig = lane & 3;
    const int wm   = wid & 3, wn = wid >> 2;
    const int rm   = wm * 32;          // warp row base within block tile
    const int cnW  = wn * 64;          // warp col base within 128-code chunk
    const int rowBase = blockIdx.x * 128;

    for (int i = tid; i < 1024; i += 256) SCBN[i] = cbn[i];

    // stage x tile: 128 rows x 256 d, fp32 -> bf16, swizzled 16B units
    {
        int r = tid >> 1, h = tid & 1;
        const float4* xp = (const float4*)(x + (size_t)(rowBase + r) * D_DIM + h * 128);
#pragma unroll
        for (int j = 0; j < 16; ++j) {
            float4 v0 = xp[2 * j], v1 = xp[2 * j + 1];
            __nv_bfloat162 p0 = __floats2bfloat162_rn(v0.x, v0.y);
            __nv_bfloat162 p1 = __floats2bfloat162_rn(v0.z, v0.w);
            __nv_bfloat162 p2 = __floats2bfloat162_rn(v1.x, v1.y);
            __nv_bfloat162 p3 = __floats2bfloat162_rn(v1.z, v1.w);
            uint4 u;
            u.x = *(uint32_t*)&p0; u.y = *(uint32_t*)&p1;
            u.z = *(uint32_t*)&p2; u.w = *(uint32_t*)&p3;
            int ui = h * 16 + j;
            *(uint4*)(sm + r * 512 + ((ui ^ (r & 7)) << 4)) = u;
        }
    }
    __syncthreads();

    // candidate state: 4 row-slots x top-3
    float cv[4][3]; int ck[4][3];
#pragma unroll
    for (int i = 0; i < 4; ++i)
#pragma unroll
        for (int t = 0; t < 3; ++t) { cv[i][t] = FLT_BIG; ck[i][t] = 0; }

    float acc[2][8][4];

    const int lc = tid >> 1, lh = tid & 1;   // se load: code row, half
    // prologue: load stage 0
    {
        const __nv_bfloat16* src = cbb + (size_t)lc * D_DIM + 0;
#pragma unroll
        for (int j = 0; j < 4; ++j) {
            int u = lh * 4 + j;
            cpasync16(smb + 65536 + lc * 128 + ((u ^ (lc & 7)) << 4), src + u * 8);
        }
    }
    cpcommit();

    for (int s = 0; s < 32; ++s) {
        // issue next stage's cp.async
        if (s + 1 < 32) {
            int chunk1 = (s + 1) >> 2, ds1 = (s + 1) & 3;
            const __nv_bfloat16* src =
                cbb + (size_t)(chunk1 * 128 + lc) * D_DIM + ds1 * 64;
            uint32_t dst = smb + 65536 + ((s + 1) & 1) * 16384 + lc * 128;
#pragma unroll
            for (int j = 0; j < 4; ++j) {
                int u = lh * 4 + j;
                cpasync16(dst + ((u ^ (lc & 7)) << 4), src + u * 8);
            }
        }
        cpcommit();
        cpwait1();
        __syncthreads();

        const int chunk = s >> 2, ds = s & 3;
        const uint32_t bufb = smb + 65536 + (s & 1) * 16384;

        if (ds == 0) {
#pragma unroll
            for (int mi = 0; mi < 2; ++mi)
#pragma unroll
                for (int nj = 0; nj < 8; ++nj)
#pragma unroll
                    for (int q = 0; q < 4; ++q) acc[mi][nj][q] = 0.f;
        }

        const int m = lane >> 3, rr = lane & 7;
#pragma unroll
        for (int ks = 0; ks < 4; ++ks) {
            uint32_t a[2][4];
#pragma unroll
            for (int mi = 0; mi < 2; ++mi) {
                int row = rm + mi * 16 + (m & 1) * 8 + rr;
                int u = ds * 8 + ks * 2 + (m >> 1);
                ldsm4(smb + row * 512 + ((u ^ (row & 7)) << 4),
                      a[mi][0], a[mi][1], a[mi][2], a[mi][3]);
            }
#pragma unroll
            for (int nh = 0; nh < 2; ++nh) {
                uint32_t b[2][4];
#pragma unroll
                for (int g = 0; g < 2; ++g) {
                    int cr = cnW + nh * 32 + g * 16 + (m & 1) * 8 + rr;
                    int u = ks * 2 + (m >> 1);
                    ldsm4(bufb + cr * 128 + ((u ^ (cr & 7)) << 4),
                          b[g][0], b[g][1], b[g][2], b[g][3]);
                }
#pragma unroll
                for (int mi = 0; mi < 2; ++mi)
#pragma unroll
                    for (int g = 0; g < 2; ++g) {
                        int nj = nh * 4 + g * 2;
                        mma16816(acc[mi][nj],     a[mi], b[g][0], b[g][2]);
                        mma16816(acc[mi][nj + 1], a[mi], b[g][1], b[g][3]);
                    }
            }
        }

        if (ds == 3) {   // chunk done: fold scores into top-3 per row-slot
            const int kbase = chunk * 128 + cnW;
#pragma unroll
            for (int mi = 0; mi < 2; ++mi)
#pragma unroll
                for (int nj = 0; nj < 8; ++nj) {
                    int k0g = kbase + nj * 8 + 2 * tig;
                    float bn0 = SCBN[k0g], bn1 = SCBN[k0g + 1];
                    float s00 = fmaf(-2.f, acc[mi][nj][0], bn0);
                    float s01 = fmaf(-2.f, acc[mi][nj][1], bn1);
                    float s10 = fmaf(-2.f, acc[mi][nj][2], bn0);
                    float s11 = fmaf(-2.f, acc[mi][nj][3], bn1);
                    int r0 = mi * 2, r1 = mi * 2 + 1;
                    ins3(s00, k0g,     cv[r0][0], cv[r0][1], cv[r0][2], ck[r0][0], ck[r0][1], ck[r0][2]);
                    ins3(s01, k0g + 1, cv[r0][0], cv[r0][1], cv[r0][2], ck[r0][0], ck[r0][1], ck[r0][2]);
                    ins3(s10, k0g,     cv[r1][0], cv[r1][1], cv[r1][2], ck[r1][0], ck[r1][1], ck[r1][2]);
                    ins3(s11, k0g + 1, cv[r1][0], cv[r1][1], cv[r1][2], ck[r1][0], ck[r1][1], ck[r1][2]);
                }
        }
        __syncthreads();
    }

    // merge: 8 owners x 3 -> global top-8 per row (via smem, reuse SE region)
    float* MV = (float*)(sm + 65536);
    int*   MK = (int*)(sm + 65536 + 12288);
    const int owner = wn * 4 + tig;
#pragma unroll
    for (int ri = 0; ri < 4; ++ri) {
        int rloc = rm + (ri >> 1) * 16 + (ri & 1) * 8 + gid;
#pragma unroll
        for (int t = 0; t < 3; ++t) {
            MV[rloc * 24 + owner * 3 + t] = cv[ri][t];
            MK[rloc * 24 + owner * 3 + t] = ck[ri][t];
        }
    }
    __syncthreads();
    if (tid < 128) {
        float* mv = MV + tid * 24;
        int*   mk = MK + tid * 24;
#pragma unroll 1
        for (int t = 0; t < 8; ++t) {
            float bv = mv[0]; int bk = mk[0]; int bp = 0;
            for (int j = 1; j < 24; ++j) {
                float v = mv[j]; int kk = mk[j];
                if (v < bv || (v == bv && kk < bk)) { bv = v; bk = kk; bp = j; }
            }
            mv[bp] = FLT_BIG;
            cand[(size_t)(rowBase + tid) * 8 + t] = bk;
        }
    }
}

// ---------------------------------------------------------------------------
// refine: exact fp32 distances on 8 candidates/row; replicates round-2 math
//   warp per row, 4 lanes per candidate (full 32B sectors)
// ---------------------------------------------------------------------------
__global__ void __launch_bounds__(256)
refine_kernel(const float* __restrict__ x, const float* __restrict__ cb,
              const float* __restrict__ cbn, const int* __restrict__ cand,
              int* __restrict__ bestidx)
{
    __shared__ float4 sxr[8][64];
    int tid = threadIdx.x, lane = tid & 31, wid = tid >> 5;
    int row = blockIdx.x * 8 + wid;

    const float4* xp = (const float4*)(x + (size_t)row * D_DIM);
    float4 v0 = xp[lane * 2], v1 = xp[lane * 2 + 1];
    sxr[wid][lane * 2] = v0;
    sxr[wid][lane * 2 + 1] = v1;
    float an = v0.x*v0.x + v0.y*v0.y + v0.z*v0.z + v0.w*v0.w
             + v1.x*v1.x + v1.y*v1.y + v1.z*v1.z + v1.w*v1.w;
#pragma unroll
    for (int o = 16; o > 0; o >>= 1) an += __shfl_xor_sync(0xffffffffu, an, o);
    __syncwarp();

    int ci = lane >> 2, q = lane & 3;
    int k = cand[(size_t)row * 8 + ci];
    const float4* ep = (const float4*)(cb + (size_t)k * D_DIM);
    float acc = 0.f;
#pragma unroll
    for (int j = 0; j < 16; ++j) {
        float4 e  = ep[q + 4 * j];
        float4 xv = sxr[wid][q + 4 * j];
        acc = fmaf(xv.x, e.x, acc);
        acc = fmaf(xv.y, e.y, acc);
        acc = fmaf(xv.z, e.z, acc);
        acc = fmaf(xv.w, e.w, acc);
    }
    acc += __shfl_xor_sync(0xffffffffu, acc, 1);
    acc += __shfl_xor_sync(0xffffffffu, acc, 2);

    float t = an + cbn[k];
    float dist = t - 2.0f * acc;
#pragma unroll
    for (int o = 4; o <= 16; o <<= 1) {
        float d2 = __shfl_xor_sync(0xffffffffu, dist, o);
        int   k2 = __shfl_xor_sync(0xffffffffu, k, o);
        if (d2 < dist || (d2 == dist && k2 < k)) { dist = d2; k = k2; }
    }
    if (lane == 0) bestidx[row] = k;
}

// ---------------------------------------------------------------------------
// gather + loss (unchanged from round 2)
// ---------------------------------------------------------------------------
__global__ void gather_kernel(const float* __restrict__ x, const float* __restrict__ cb,
                              const int* __restrict__ idx,
                              float* __restrict__ outq, float* __restrict__ outidx,
                              float* __restrict__ partial, int N)
{
    __shared__ float ssum[8];
    int gw   = (blockIdx.x * blockDim.x + threadIdx.x) >> 5;
    int lane = threadIdx.x & 31;
    float s = 0.f;
    if (gw < N) {
        int k = idx[gw];
        const float4* cp = (const float4*)(cb + (size_t)k * D_DIM);
        const float4* xp = (const float4*)(x + (size_t)gw * D_DIM);
        float4* op = (float4*)(outq + (size_t)gw * D_DIM);
#pragma unroll
        for (int i = 0; i < 2; ++i) {
            float4 q = cp[lane + 32 * i];
            float4 v = xp[lane + 32 * i];
            float dx = q.x - v.x, dy = q.y - v.y, dz = q.z - v.z, dw = q.w - v.w;
            s += dx * dx + dy * dy + dz * dz + dw * dw;
            op[lane + 32 * i] = q;
        }
        if (lane == 0 && outidx) outidx[gw] = (float)k;
    }
#pragma unroll
    for (int o = 16; o > 0; o >>= 1) s += __shfl_xor_sync(0xffffffffu, s, o);
    int w = threadIdx.x >> 5;
    if (lane == 0) ssum[w] = s;
    __syncthreads();
    if (threadIdx.x == 0) {
        float t = 0.f;
        for (int i = 0; i < 8; ++i) t += ssum[i];
        partial[blockIdx.x] = t;
    }
}

__global__ void loss_kernel(const float* __restrict__ partial, int n,
                            float* __restrict__ lossOut, float inv)
{
    int lane = threadIdx.x & 31;
    float s = 0.f;
    for (int i = lane; i < n; i += 32) s += partial[i];
#pragma unroll
    for (int o = 16; o > 0; o >>= 1) s += __shfl_xor_sync(0xffffffffu, s, o);
    if (lane == 0 && lossOut) *lossOut = s * inv;
}

// ---------------------------------------------------------------------------
extern "C" void kernel_launch(void* const* d_in, const int* in_sizes, int n_in,
                              void* d_out, int out_size)
{
    const float* x  = (const float*)d_in[0];
    const float* cb = (const float*)d_in[1];
    int N = in_sizes[0] / D_DIM;   // 32768
    // int K = in_sizes[1] / D_DIM;  // 1024 (hard-assumed by coarse kernel)

    float* out  = (float*)d_out;
    float* outq = out;
    long long qn  = (long long)N * D_DIM;
    long long rem = (long long)out_size - qn;
    float* outidx  = nullptr;
    float* outloss = nullptr;
    if (rem >= (long long)N) {
        outidx = out + qn;
        if (rem >= (long long)N + 1) outloss = out + qn + N;
    } else if (rem >= 1) {
        outloss = out + qn;
    }

    __nv_bfloat16* cbb; float *cbn, *part; int *cnd, *bidx;
    cudaGetSymbolAddress((void**)&cbb,  g_cbb);
    cudaGetSymbolAddress((void**)&cbn,  g_codenorm);
    cudaGetSymbolAddress((void**)&cnd,  g_cand);
    cudaGetSymbolAddress((void**)&bidx, g_bestidx);
    cudaGetSymbolAddress((void**)&part, g_partial);

    prep_cb_kernel<<<128, 256>>>(cb, cbb, cbn);

    cudaFuncSetAttribute(coarse_kernel,
                         cudaFuncAttributeMaxDynamicSharedMemorySize, CO_SMEM);
    coarse_kernel<<<N / 128, 256, CO_SMEM>>>(x, cbb, cbn, cnd);

    refine_kernel<<<N / 8, 256>>>(x, cb, cbn, cnd, bidx);

    int warpBlocksN = (N * 32 + 255) / 256;
    gather_kernel<<<warpBlocksN, 256>>>(x, cb, bidx, outq, outidx, part, N);
    loss_kernel<<<1, 32>>>(part, warpBlocksN, outloss,
                           1.0f / (float)((long long)N * D_DIM));
}

// round 8
// speedup vs baseline: 3.8006x; 1.1598x over previous
#include <cuda_runtime.h>
#include <cuda_bf16.h>
#include <cstdint>

#define D_DIM 256
#define FLT_BIG 3.402823466e+38f
#define NCAND 4

// scratch (static device globals; no allocations)
__device__ __nv_bfloat16 g_cbb[1024 * 256];
__device__ float g_codenorm[1024];
__device__ int   g_cand[32768 * NCAND];
__device__ float g_partial[8192];

// smem layout: A tile 64KB | B ring 3x16KB
#define OFF_B   65536
#define CO_SMEM (65536 + 49152)   // 114688 -> 2 CTAs/SM

// ---------------------------------------------------------------------------
// PTX helpers (plain sm_103: mma.sync + ldmatrix + cp.async only)
// ---------------------------------------------------------------------------
__device__ __forceinline__ void ldsm4(uint32_t addr, uint32_t& r0, uint32_t& r1,
                                      uint32_t& r2, uint32_t& r3) {
    asm volatile("ldmatrix.sync.aligned.m8n8.x4.shared.b16 {%0,%1,%2,%3}, [%4];"
                 : "=r"(r0), "=r"(r1), "=r"(r2), "=r"(r3) : "r"(addr));
}
__device__ __forceinline__ void mma16816(float* c, const uint32_t* a,
                                         uint32_t b0, uint32_t b1) {
    asm volatile(
        "mma.sync.aligned.m16n8k16.row.col.f32.bf16.bf16.f32 "
        "{%0,%1,%2,%3}, {%4,%5,%6,%7}, {%8,%9}, {%0,%1,%2,%3};"
        : "+f"(c[0]), "+f"(c[1]), "+f"(c[2]), "+f"(c[3])
        : "r"(a[0]), "r"(a[1]), "r"(a[2]), "r"(a[3]), "r"(b0), "r"(b1));
}
__device__ __forceinline__ void cpasync16(uint32_t dst, const void* src) {
    asm volatile("cp.async.cg.shared.global [%0], [%1], 16;" :: "r"(dst), "l"(src));
}
__device__ __forceinline__ void cpcommit() { asm volatile("cp.async.commit_group;"); }
__device__ __forceinline__ void cpwait1()  { asm volatile("cp.async.wait_group 1;"); }

__device__ __forceinline__ void ins3(float s, int k,
                                     float& v0, float& v1, float& v2,
                                     int& k0, int& k1, int& k2) {
    if (s < v2) {
        if (s < v0)      { v2 = v1; k2 = k1; v1 = v0; k1 = k0; v0 = s; k0 = k; }
        else if (s < v1) { v2 = v1; k2 = k1; v1 = s;  k1 = k; }
        else             { v2 = s;  k2 = k; }
    }
}

// ---------------------------------------------------------------------------
// prep: codebook -> bf16, code norms (fp32)
// ---------------------------------------------------------------------------
__global__ void prep_cb_kernel(const float* __restrict__ cb,
                               __nv_bfloat16* __restrict__ cbb,
                               float* __restrict__ cbn)
{
    int gw   = (blockIdx.x * blockDim.x + threadIdx.x) >> 5;
    int lane = threadIdx.x & 31;
    if (gw >= 1024) return;
    const float4* p = (const float4*)(cb + (size_t)gw * D_DIM);
    float4 v0 = p[lane * 2], v1 = p[lane * 2 + 1];
    float s = v0.x*v0.x + v0.y*v0.y + v0.z*v0.z + v0.w*v0.w
            + v1.x*v1.x + v1.y*v1.y + v1.z*v1.z + v1.w*v1.w;
#pragma unroll
    for (int o = 16; o > 0; o >>= 1) s += __shfl_xor_sync(0xffffffffu, s, o);
    if (lane == 0) cbn[gw] = s;
    __nv_bfloat162 b0 = __floats2bfloat162_rn(v0.x, v0.y);
    __nv_bfloat162 b1 = __floats2bfloat162_rn(v0.z, v0.w);
    __nv_bfloat162 b2 = __floats2bfloat162_rn(v1.x, v1.y);
    __nv_bfloat162 b3 = __floats2bfloat162_rn(v1.z, v1.w);
    uint4 u;
    u.x = *(uint32_t*)&b0; u.y = *(uint32_t*)&b1;
    u.z = *(uint32_t*)&b2; u.w = *(uint32_t*)&b3;
    *(uint4*)(cbb + (size_t)gw * D_DIM + lane * 8) = u;
}

// ---------------------------------------------------------------------------
// coarse: bf16 mma.sync distance pass, top-4 candidates per row
//   block = 128 rows x 1024 codes (8 chunks of 128), d-slices of 64
//   triple-buffered B ring, ONE barrier per stage
// ---------------------------------------------------------------------------
__global__ void __launch_bounds__(256, 2)
coarse_kernel(const float* __restrict__ x, const __nv_bfloat16* __restrict__ cbb,
              const float* __restrict__ cbn, int* __restrict__ cand)
{
    extern __shared__ char sm[];
    const uint32_t smb = (uint32_t)__cvta_generic_to_shared(sm);

    const int tid  = threadIdx.x;
    const int lane = tid & 31, wid = tid >> 5;
    const int gid  = lane >> 2, tig = lane & 3;
    const int wm   = wid & 3, wn = wid >> 2;
    const int rm   = wm * 32;          // warp row base within block tile
    const int cnW  = wn * 64;          // warp col base within 128-code chunk
    const int rowBase = blockIdx.x * 128;

    const int lc = tid >> 1, lh = tid & 1;   // B loads: code row, half

    // stage x tile: 128 rows x 256 d, fp32 -> bf16, swizzled 16B units
    {
        int r = tid >> 1, h = tid & 1;
        const float4* xp = (const float4*)(x + (size_t)(rowBase + r) * D_DIM + h * 128);
#pragma unroll
        for (int j = 0; j < 16; ++j) {
            float4 v0 = xp[2 * j], v1 = xp[2 * j + 1];
            __nv_bfloat162 p0 = __floats2bfloat162_rn(v0.x, v0.y);
            __nv_bfloat162 p1 = __floats2bfloat162_rn(v0.z, v0.w);
            __nv_bfloat162 p2 = __floats2bfloat162_rn(v1.x, v1.y);
            __nv_bfloat162 p3 = __floats2bfloat162_rn(v1.z, v1.w);
            uint4 u;
            u.x = *(uint32_t*)&p0; u.y = *(uint32_t*)&p1;
            u.z = *(uint32_t*)&p2; u.w = *(uint32_t*)&p3;
            int ui = h * 16 + j;
            *(uint4*)(sm + r * 512 + ((ui ^ (r & 7)) << 4)) = u;
        }
    }

    // B ring loader for stage t (buf = t % 3), 64-d slice of a 128-code chunk
    auto stage_load = [&](int t) {
        const __nv_bfloat16* src =
            cbb + (size_t)((t >> 2) * 128 + lc) * D_DIM + (t & 3) * 64;
        uint32_t dst = smb + OFF_B + (uint32_t)(t % 3) * 16384u + lc * 128;
#pragma unroll
        for (int j = 0; j < 4; ++j) {
            int u = lh * 4 + j;
            cpasync16(dst + ((u ^ (lc & 7)) << 4), src + u * 8);
        }
    };

    stage_load(0); cpcommit();
    stage_load(1); cpcommit();

    // candidate state: 4 row-slots x top-3
    float cv[4][3]; int ck[4][3];
#pragma unroll
    for (int i = 0; i < 4; ++i)
#pragma unroll
        for (int t = 0; t < 3; ++t) { cv[i][t] = FLT_BIG; ck[i][t] = 0; }

    float acc[2][8][4];
    const int m = lane >> 3, rr = lane & 7;

    for (int s = 0; s < 32; ++s) {
        cpwait1();            // group s complete (pending <= group s+1)
        __syncthreads();      // all warps: buffer s visible, stage s-1 compute done
        if (s + 2 < 32) stage_load(s + 2);   // buf (s+2)%3 == (s-1)%3: free now
        cpcommit();

        const int chunk = s >> 2, ds = s & 3;
        const uint32_t bufb = smb + OFF_B + (uint32_t)(s % 3) * 16384u;

        if (ds == 0) {
#pragma unroll
            for (int mi = 0; mi < 2; ++mi)
#pragma unroll
                for (int nj = 0; nj < 8; ++nj)
#pragma unroll
                    for (int q = 0; q < 4; ++q) acc[mi][nj][q] = 0.f;
        }

#pragma unroll
        for (int ks = 0; ks < 4; ++ks) {
            uint32_t a[2][4];
#pragma unroll
            for (int mi = 0; mi < 2; ++mi) {
                int row = rm + mi * 16 + (m & 1) * 8 + rr;
                int u = ds * 8 + ks * 2 + (m >> 1);
                ldsm4(smb + row * 512 + ((u ^ (row & 7)) << 4),
                      a[mi][0], a[mi][1], a[mi][2], a[mi][3]);
            }
#pragma unroll
            for (int nh = 0; nh < 2; ++nh) {
                uint32_t b[2][4];
#pragma unroll
                for (int g = 0; g < 2; ++g) {
                    int cr = cnW + nh * 32 + g * 16 + (m & 1) * 8 + rr;
                    int u = ks * 2 + (m >> 1);
                    ldsm4(bufb + cr * 128 + ((u ^ (cr & 7)) << 4),
                          b[g][0], b[g][1], b[g][2], b[g][3]);
                }
#pragma unroll
                for (int mi = 0; mi < 2; ++mi)
#pragma unroll
                    for (int g = 0; g < 2; ++g) {
                        int nj = nh * 4 + g * 2;
                        mma16816(acc[mi][nj],     a[mi], b[g][0], b[g][2]);
                        mma16816(acc[mi][nj + 1], a[mi], b[g][1], b[g][3]);
                    }
            }
        }

        if (ds == 3) {   // chunk done: fold scores into top-3 per row-slot
            const int kbase = chunk * 128 + cnW;
#pragma unroll
            for (int mi = 0; mi < 2; ++mi)
#pragma unroll
                for (int nj = 0; nj < 8; ++nj) {
                    int k0g = kbase + nj * 8 + 2 * tig;
                    float bn0 = __ldg(cbn + k0g), bn1 = __ldg(cbn + k0g + 1);
                    float s00 = fmaf(-2.f, acc[mi][nj][0], bn0);
                    float s01 = fmaf(-2.f, acc[mi][nj][1], bn1);
                    float s10 = fmaf(-2.f, acc[mi][nj][2], bn0);
                    float s11 = fmaf(-2.f, acc[mi][nj][3], bn1);
                    int r0 = mi * 2, r1 = mi * 2 + 1;
                    ins3(s00, k0g,     cv[r0][0], cv[r0][1], cv[r0][2], ck[r0][0], ck[r0][1], ck[r0][2]);
                    ins3(s01, k0g + 1, cv[r0][0], cv[r0][1], cv[r0][2], ck[r0][0], ck[r0][1], ck[r0][2]);
                    ins3(s10, k0g,     cv[r1][0], cv[r1][1], cv[r1][2], ck[r1][0], ck[r1][1], ck[r1][2]);
                    ins3(s11, k0g + 1, cv[r1][0], cv[r1][1], cv[r1][2], ck[r1][0], ck[r1][1], ck[r1][2]);
                }
        }
    }

    // merge: 8 owners x top-3 -> global top-4 per row (smem in B-ring region)
    __syncthreads();
    float* MV = (float*)(sm + OFF_B);
    int*   MK = (int*)(sm + OFF_B + 12288);
    const int owner = wn * 4 + tig;
#pragma unroll
    for (int ri = 0; ri < 4; ++ri) {
        int rloc = rm + (ri >> 1) * 16 + (ri & 1) * 8 + gid;
#pragma unroll
        for (int t = 0; t < 3; ++t) {
            MV[rloc * 24 + owner * 3 + t] = cv[ri][t];
            MK[rloc * 24 + owner * 3 + t] = ck[ri][t];
        }
    }
    __syncthreads();
    if (tid < 128) {
        float* mv = MV + tid * 24;
        int*   mk = MK + tid * 24;
#pragma unroll 1
        for (int t = 0; t < NCAND; ++t) {
            float bv = mv[0]; int bk = mk[0]; int bp = 0;
            for (int j = 1; j < 24; ++j) {
                float v = mv[j]; int kk = mk[j];
                if (v < bv || (v == bv && kk < bk)) { bv = v; bk = kk; bp = j; }
            }
            mv[bp] = FLT_BIG;
            cand[(size_t)(rowBase + tid) * NCAND + t] = bk;
        }
    }
}

// ---------------------------------------------------------------------------
// finalize: exact fp32 refine over 4 candidates + gather + loss partial
//   warp per row; 8 lanes per candidate
// ---------------------------------------------------------------------------
__global__ void __launch_bounds__(256)
finalize_kernel(const float* __restrict__ x, const float* __restrict__ cb,
                const float* __restrict__ cbn, const int* __restrict__ cand,
                float* __restrict__ outq, float* __restrict__ outidx,
                float* __restrict__ partial)
{
    __shared__ float4 sxr[8][64];
    __shared__ float ssum[8];
    int tid = threadIdx.x, lane = tid & 31, wid = tid >> 5;
    int row = blockIdx.x * 8 + wid;

    const float4* xp = (const float4*)(x + (size_t)row * D_DIM);
    float4 v0 = xp[lane * 2], v1 = xp[lane * 2 + 1];
    sxr[wid][lane * 2] = v0;
    sxr[wid][lane * 2 + 1] = v1;
    float an = v0.x*v0.x + v0.y*v0.y + v0.z*v0.z + v0.w*v0.w
             + v1.x*v1.x + v1.y*v1.y + v1.z*v1.z + v1.w*v1.w;
#pragma unroll
    for (int o = 16; o > 0; o >>= 1) an += __shfl_xor_sync(0xffffffffu, an, o);
    __syncwarp();

    int ci = lane >> 3, q = lane & 7;
    int k = cand[(size_t)row * NCAND + ci];
    const float4* ep = (const float4*)(cb + (size_t)k * D_DIM);
    float acc = 0.f;
#pragma unroll
    for (int j = 0; j < 8; ++j) {
        float4 e  = ep[q + 8 * j];
        float4 xv = sxr[wid][q + 8 * j];
        acc = fmaf(xv.x, e.x, acc);
        acc = fmaf(xv.y, e.y, acc);
        acc = fmaf(xv.z, e.z, acc);
        acc = fmaf(xv.w, e.w, acc);
    }
    acc += __shfl_xor_sync(0xffffffffu, acc, 1);
    acc += __shfl_xor_sync(0xffffffffu, acc, 2);
    acc += __shfl_xor_sync(0xffffffffu, acc, 4);

    float t = an + cbn[k];
    float dist = t - 2.0f * acc;
#pragma unroll
    for (int o = 8; o <= 16; o <<= 1) {
        float d2 = __shfl_xor_sync(0xffffffffu, dist, o);
        int   k2 = __shfl_xor_sync(0xffffffffu, k, o);
        if (d2 < dist || (d2 == dist && k2 < k)) { dist = d2; k = k2; }
    }

    // gather + loss with the winning code
    const float4* cp = (const float4*)(cb + (size_t)k * D_DIM);
    float4* op = (float4*)(outq + (size_t)row * D_DIM);
    float4 q0 = cp[lane * 2], q1 = cp[lane * 2 + 1];
    op[lane * 2] = q0;
    op[lane * 2 + 1] = q1;
    float dx0 = q0.x - v0.x, dy0 = q0.y - v0.y, dz0 = q0.z - v0.z, dw0 = q0.w - v0.w;
    float dx1 = q1.x - v1.x, dy1 = q1.y - v1.y, dz1 = q1.z - v1.z, dw1 = q1.w - v1.w;
    float s = dx0*dx0 + dy0*dy0 + dz0*dz0 + dw0*dw0
            + dx1*dx1 + dy1*dy1 + dz1*dz1 + dw1*dw1;
#pragma unroll
    for (int o = 16; o > 0; o >>= 1) s += __shfl_xor_sync(0xffffffffu, s, o);
    if (lane == 0) {
        ssum[wid] = s;
        if (outidx) outidx[row] = (float)k;
    }
    __syncthreads();
    if (tid == 0) {
        float tt = 0.f;
        for (int i = 0; i < 8; ++i) tt += ssum[i];
        partial[blockIdx.x] = tt;
    }
}

__global__ void loss_kernel(const float* __restrict__ partial, int n,
                            float* __restrict__ lossOut, float inv)
{
    int lane = threadIdx.x & 31;
    float s = 0.f;
    for (int i = lane; i < n; i += 32) s += partial[i];
#pragma unroll
    for (int o = 16; o > 0; o >>= 1) s += __shfl_xor_sync(0xffffffffu, s, o);
    if (lane == 0 && lossOut) *lossOut = s * inv;
}

// ---------------------------------------------------------------------------
extern "C" void kernel_launch(void* const* d_in, const int* in_sizes, int n_in,
                              void* d_out, int out_size)
{
    const float* x  = (const float*)d_in[0];
    const float* cb = (const float*)d_in[1];
    int N = in_sizes[0] / D_DIM;   // 32768

    float* out  = (float*)d_out;
    float* outq = out;
    long long qn  = (long long)N * D_DIM;
    long long rem = (long long)out_size - qn;
    float* outidx  = nullptr;
    float* outloss = nullptr;
    if (rem >= (long long)N) {
        outidx = out + qn;
        if (rem >= (long long)N + 1) outloss = out + qn + N;
    } else if (rem >= 1) {
        outloss = out + qn;
    }

    __nv_bfloat16* cbb; float *cbn, *part; int *cnd;
    cudaGetSymbolAddress((void**)&cbb,  g_cbb);
    cudaGetSymbolAddress((void**)&cbn,  g_codenorm);
    cudaGetSymbolAddress((void**)&cnd,  g_cand);
    cudaGetSymbolAddress((void**)&part, g_partial);

    prep_cb_kernel<<<128, 256>>>(cb, cbb, cbn);

    cudaFuncSetAttribute(coarse_kernel,
                         cudaFuncAttributeMaxDynamicSharedMemorySize, CO_SMEM);
    coarse_kernel<<<N / 128, 256, CO_SMEM>>>(x, cbb, cbn, cnd);

    int fblocks = N / 8;
    finalize_kernel<<<fblocks, 256>>>(x, cb, cbn, cnd, outq, outidx, part);
    loss_kernel<<<1, 32>>>(part, fblocks, outloss,
                           1.0f / (float)((long long)N * D_DIM));
}